// round 8
// baseline (speedup 1.0000x reference)
#include <cuda_runtime.h>
#include <math.h>

// ---------------------------------------------------------------------------
// ImageSectionRNNCell — B=64, image 512x512x3, grid 16x16, U=256
// out layout: h_new[64*256] | c_new[64*256] | next_section[64*3]
//
// 6 launches:
//  K1 (grid 128): blocks 0-63  front (interp+conv+bias-init g_y/g_ns)
//                 blocks 64-127 recurrent LSTM partial h0@lstm_rk -> g_z (atomic)
//  K2 (grid 128): dense partial xs@dw -> g_y (atomic, bias-pre-init)
//  K3 (grid 64):  input LSTM partial relu(g_y)@lstm_k -> g_z (atomic)
//  K4 (grid 64):  gates: read g_z (+self-reset to 0), +lb, nonlin -> out h/c
//  K5 (grid 64):  nsc1 partial h@w1 -> g_ns (atomic, bias-pre-init)
//  K6 (grid 64):  nsc2 -> out section
// g_z is zero on entry to every run (module-load zero init + K4 self-reset).
// ---------------------------------------------------------------------------

#define B 64
#define U 256
#define IMGH 512
#define IMGW 512

__device__ float g_xs[B * 432];     // conv2 output (dense input)
__device__ float g_y [B * U];       // dense pre-act accumulator (bias-init K1)
__device__ float g_z [B][4 * U];    // LSTM pre-act accumulator (zero invariant)
__device__ float g_ns[B * U];       // nsc1 pre-act accumulator (bias-init K1)

__device__ __forceinline__ float sigmoidf_(float x) {
    return 1.0f / (1.0f + __expf(-x));
}

// ---- shared LSTM partial-tile worker --------------------------------------
// dsm layout: act[64][132] then wt[128][36]. Computes 32 z-cols (ct) over a
// 128-deep k-slice and atomically accumulates into g_z.
__device__ __forceinline__ void lstm_partial(float* dsm,
                                             const float* __restrict__ actbase,
                                             bool do_relu,
                                             const float* __restrict__ wbase,
                                             int ct, int t)
{
    float (*act)[132] = (float(*)[132])dsm;
    float (*wt)[36]   = (float(*)[36])(dsm + 64 * 132);

    for (int i = t; i < 64 * 32; i += 256) {
        const int row = i >> 5;
        const int c4  = i & 31;
        float4 v = *(const float4*)(actbase + row * U + c4 * 4);
        if (do_relu) {
            v.x = fmaxf(v.x, 0.f); v.y = fmaxf(v.y, 0.f);
            v.z = fmaxf(v.z, 0.f); v.w = fmaxf(v.w, 0.f);
        }
        *(float4*)&act[row][c4 * 4] = v;
    }
    for (int i = t; i < 128 * 8; i += 256) {
        const int row = i >> 3;
        const int c4  = i & 7;
        const float4 w = *(const float4*)(wbase + (size_t)row * 1024 + ct * 32 + c4 * 4);
        *(float4*)&wt[row][c4 * 4] = w;
    }
    __syncthreads();

    const int c4 = t & 7;        // 4 cols: ct*32 + c4*4 ..
    const int bp = t >> 3;       // batches bp, bp+32
    float s00 = 0.f, s01 = 0.f, s02 = 0.f, s03 = 0.f;
    float s10 = 0.f, s11 = 0.f, s12 = 0.f, s13 = 0.f;
    #pragma unroll 4
    for (int k = 0; k < 128; k++) {
        const float a0 = act[bp][k];
        const float a1 = act[bp + 32][k];
        const float4 w = *(const float4*)&wt[k][c4 * 4];
        s00 += a0 * w.x; s01 += a0 * w.y; s02 += a0 * w.z; s03 += a0 * w.w;
        s10 += a1 * w.x; s11 += a1 * w.y; s12 += a1 * w.z; s13 += a1 * w.w;
    }
    const int col = ct * 32 + c4 * 4;
    atomicAdd(&g_z[bp][col + 0], s00);
    atomicAdd(&g_z[bp][col + 1], s01);
    atomicAdd(&g_z[bp][col + 2], s02);
    atomicAdd(&g_z[bp][col + 3], s03);
    atomicAdd(&g_z[bp + 32][col + 0], s10);
    atomicAdd(&g_z[bp + 32][col + 1], s11);
    atomicAdd(&g_z[bp + 32][col + 2], s12);
    atomicAdd(&g_z[bp + 32][col + 3], s13);
}

// ===========================================================================
// K1: blocks 0-63: front (bias-init + interp + conv1 + conv2 -> g_xs)
//     blocks 64-127: recurrent LSTM partial (h0 @ lstm_rk, 2 ktiles x 32 cols)
// dynamic smem 52224 B
// ===========================================================================
__global__ __launch_bounds__(256, 1)
void k1_mixed(const float* __restrict__ image,
              const float* __restrict__ section,
              const float* __restrict__ c1k, const float* __restrict__ c1b,
              const float* __restrict__ c2k, const float* __restrict__ c2b,
              const float* __restrict__ db,  const float* __restrict__ b1,
              const float* __restrict__ h0,  const float* __restrict__ lrk)
{
    extern __shared__ float dsm[];
    const int t = threadIdx.x;

    if (blockIdx.x >= B) {
        // ---- recurrent LSTM partial ----
        const int bid = blockIdx.x - B;
        const int ct = bid & 31;
        const int kt = bid >> 5;           // 0 or 1
        lstm_partial(dsm, h0 + kt * 128, false,
                     lrk + (size_t)kt * 128 * 1024, ct, t);
        return;
    }

    // ---- front ----
    const int b = blockIdx.x;
    float* sec = dsm;              // 768 floats
    float* c1o = dsm + 768;        // 588 floats

    g_y [b * U + t] = db[t];
    g_ns[b * U + t] = b1[t];

    {
        const float s0 = section[b * 3 + 0];
        const float s1 = section[b * 3 + 1];
        const float ee = section[b * 3 + 2];
        const int i = t >> 4;
        const int j = t & 15;
        const float p0 = s0 + (float)i * (1.0f / 15.0f) * ee;
        const float p1 = s1 + (float)j * (1.0f / 15.0f) * ee;
        float fy = fminf(fmaxf(p0 * (float)(IMGH - 1), 0.0f), (float)(IMGH - 1));
        float fx = fminf(fmaxf(p1 * (float)(IMGW - 1), 0.0f), (float)(IMGW - 1));
        int y0 = (int)floorf(fy);
        int x0 = (int)floorf(fx);
        int y1 = min(y0 + 1, IMGH - 1);
        int x1 = min(x0 + 1, IMGW - 1);
        float wy = fy - (float)y0;
        float wx = fx - (float)x0;
        const float* img = image + (size_t)b * IMGH * IMGW * 3;
        const float* p00 = img + ((size_t)y0 * IMGW + x0) * 3;
        const float* p01 = img + ((size_t)y0 * IMGW + x1) * 3;
        const float* p10 = img + ((size_t)y1 * IMGW + x0) * 3;
        const float* p11 = img + ((size_t)y1 * IMGW + x1) * 3;
        #pragma unroll
        for (int c = 0; c < 3; c++) {
            float top = p00[c] * (1.0f - wx) + p01[c] * wx;
            float bot = p10[c] * (1.0f - wx) + p11[c] * wx;
            sec[(i * 16 + j) * 3 + c] = top * (1.0f - wy) + bot * wy;
        }
    }
    __syncthreads();

    if (t < 196) {
        const int oh = t / 14;
        const int ow = t - oh * 14;
        float a0 = c1b[0], a1 = c1b[1], a2 = c1b[2];
        #pragma unroll
        for (int kh = 0; kh < 3; kh++)
            #pragma unroll
            for (int kw = 0; kw < 3; kw++) {
                const float* s = &sec[((oh + kh) * 16 + (ow + kw)) * 3];
                const float* w = &c1k[(kh * 3 + kw) * 9];
                #pragma unroll
                for (int ic = 0; ic < 3; ic++) {
                    const float sv = s[ic];
                    a0 += sv * w[ic * 3 + 0];
                    a1 += sv * w[ic * 3 + 1];
                    a2 += sv * w[ic * 3 + 2];
                }
            }
        c1o[t * 3 + 0] = fmaxf(a0, 0.0f);
        c1o[t * 3 + 1] = fmaxf(a1, 0.0f);
        c1o[t * 3 + 2] = fmaxf(a2, 0.0f);
    }
    __syncthreads();

    if (t < 144) {
        const int oh = t / 12;
        const int ow = t - oh * 12;
        float a0 = c2b[0], a1 = c2b[1], a2 = c2b[2];
        #pragma unroll
        for (int kh = 0; kh < 3; kh++)
            #pragma unroll
            for (int kw = 0; kw < 3; kw++) {
                const float* s = &c1o[((oh + kh) * 14 + (ow + kw)) * 3];
                const float* w = &c2k[(kh * 3 + kw) * 9];
                #pragma unroll
                for (int ic = 0; ic < 3; ic++) {
                    const float sv = s[ic];
                    a0 += sv * w[ic * 3 + 0];
                    a1 += sv * w[ic * 3 + 1];
                    a2 += sv * w[ic * 3 + 2];
                }
            }
        float* dst = g_xs + b * 432 + t * 3;
        dst[0] = fmaxf(a0, 0.0f);
        dst[1] = fmaxf(a1, 0.0f);
        dst[2] = fmaxf(a2, 0.0f);
    }
}

// ===========================================================================
// K2: dense partial. 128 blocks = 32 unit-tiles (8 units) x 4 k-tiles (108).
// atomicAdd into g_y (bias pre-initialized).
// ===========================================================================
__global__ __launch_bounds__(256, 1)
void k2_dense(const float* __restrict__ dw)
{
    const int ut = blockIdx.x & 31;
    const int kt = blockIdx.x >> 5;
    const int t  = threadIdx.x;
    const int k0 = kt * 108;

    __shared__ float axs[64][112];
    __shared__ float wts[108][12];

    for (int i = t; i < 64 * 27; i += 256) {
        const int row = i / 27;
        const int c4  = i - row * 27;
        const float4 v = *(const float4*)(g_xs + row * 432 + k0 + c4 * 4);
        *(float4*)&axs[row][c4 * 4] = v;
    }
    if (t < 216) {
        const int row = t >> 1;
        const int h   = t & 1;
        const float4 w = *(const float4*)(dw + (size_t)(k0 + row) * U + ut * 8 + h * 4);
        *(float4*)&wts[row][h * 4] = w;
    }
    __syncthreads();

    const int u2 = t & 3;
    const int bp = t >> 2;
    float a0 = 0.f, a1 = 0.f, a2 = 0.f, a3 = 0.f;
    #pragma unroll 2
    for (int k = 0; k < 108; k += 2) {
        const float x0 = axs[bp][k];
        const float x1 = axs[bp][k + 1];
        const float2 w0 = *(const float2*)&wts[k][u2 * 2];
        const float2 w1 = *(const float2*)&wts[k + 1][u2 * 2];
        a0 += x0 * w0.x; a1 += x0 * w0.y;
        a2 += x1 * w1.x; a3 += x1 * w1.y;
    }
    const int u = ut * 8 + u2 * 2;
    atomicAdd(&g_y[bp * U + u],     a0 + a2);
    atomicAdd(&g_y[bp * U + u + 1], a1 + a3);
}

// ===========================================================================
// K3: input LSTM partial. 64 blocks = 32 col-tiles x 2 k-tiles.
// acts = relu(g_y), weights = lstm_k, atomicAdd -> g_z.
// ===========================================================================
__global__ __launch_bounds__(256, 1)
void k3_lstm_in(const float* __restrict__ lk)
{
    extern __shared__ float dsm[];
    const int ct = blockIdx.x & 31;
    const int kt = blockIdx.x >> 5;    // 0 or 1
    lstm_partial(dsm, g_y + kt * 128, true,
                 lk + (size_t)kt * 128 * 1024, ct, threadIdx.x);
}

// ===========================================================================
// K4: gates. 64 blocks x 256 threads, thread = (batch, unit).
// Reads g_z, self-resets it to 0 (accumulator invariant for graph replay),
// adds bias, applies LSTM nonlinearity, writes h_new/c_new.
// ===========================================================================
__global__ __launch_bounds__(256, 4)
void k4_gates(const float* __restrict__ c0in, const float* __restrict__ lb,
              float* __restrict__ out)
{
    const int b = blockIdx.x;
    const int u = threadIdx.x;

    float zi = g_z[b][u];
    float zf = g_z[b][U + u];
    float zg = g_z[b][2 * U + u];
    float zo = g_z[b][3 * U + u];
    g_z[b][u]         = 0.0f;
    g_z[b][U + u]     = 0.0f;
    g_z[b][2 * U + u] = 0.0f;
    g_z[b][3 * U + u] = 0.0f;

    zi += lb[u];
    zf += lb[U + u];
    zg += lb[2 * U + u];
    zo += lb[3 * U + u];

    const float cprev = c0in[b * U + u];
    const float cn = sigmoidf_(zf) * cprev + sigmoidf_(zi) * tanhf(zg);
    const float hn = sigmoidf_(zo) * tanhf(cn);
    out[b * U + u]         = hn;
    out[B * U + b * U + u] = cn;
}

// ===========================================================================
// K5: nsc1 partial. 64 blocks = 32 unit-tiles (8 units) x 2 k-tiles (128).
// acts = h_new (from out). atomicAdd into g_ns (bias pre-initialized).
// ===========================================================================
__global__ __launch_bounds__(256, 1)
void k5_nsc1(const float* __restrict__ w1, const float* __restrict__ out)
{
    const int ut = blockIdx.x & 31;
    const int kt = blockIdx.x >> 5;
    const int t  = threadIdx.x;

    __shared__ float axs[64][132];
    __shared__ float wts[128][12];

    for (int i = t; i < 64 * 32; i += 256) {
        const int row = i >> 5;
        const int c4  = i & 31;
        const float4 v = *(const float4*)(out + row * U + kt * 128 + c4 * 4);
        *(float4*)&axs[row][c4 * 4] = v;
    }
    {
        const int row = t >> 1;
        const int h   = t & 1;
        const float4 w = *(const float4*)(w1 + (size_t)(kt * 128 + row) * U + ut * 8 + h * 4);
        *(float4*)&wts[row][h * 4] = w;
    }
    __syncthreads();

    const int u2 = t & 3;
    const int bp = t >> 2;
    float a0 = 0.f, a1 = 0.f, a2 = 0.f, a3 = 0.f;
    #pragma unroll 4
    for (int k = 0; k < 128; k += 2) {
        const float x0 = axs[bp][k];
        const float x1 = axs[bp][k + 1];
        const float2 w0 = *(const float2*)&wts[k][u2 * 2];
        const float2 w1v = *(const float2*)&wts[k + 1][u2 * 2];
        a0 += x0 * w0.x;  a1 += x0 * w0.y;
        a2 += x1 * w1v.x; a3 += x1 * w1v.y;
    }
    const int u = ut * 8 + u2 * 2;
    atomicAdd(&g_ns[bp * U + u],     a0 + a2);
    atomicAdd(&g_ns[bp * U + u + 1], a1 + a3);
}

// ===========================================================================
// K6: nsc2. next_section = sigmoid(relu(g_ns) @ W2 + b2). 64 blocks x 96.
// ===========================================================================
__global__ __launch_bounds__(96, 8)
void k6_nsc2(const float* __restrict__ w2, const float* __restrict__ b2,
             float* __restrict__ out)
{
    const int b = blockIdx.x;
    const int t = threadIdx.x;
    const int g = t >> 5;
    const int l = t & 31;

    const float* ns = g_ns + b * U;
    float s = 0.0f;
    #pragma unroll
    for (int k = l; k < U; k += 32)
        s += fmaxf(ns[k], 0.0f) * w2[k * 3 + g];
    #pragma unroll
    for (int o = 16; o > 0; o >>= 1)
        s += __shfl_down_sync(0xffffffffu, s, o);
    if (l == 0)
        out[2 * B * U + b * 3 + g] = sigmoidf_(s + b2[g]);
}

// ===========================================================================
extern "C" void kernel_launch(void* const* d_in, const int* in_sizes, int n_in,
                              void* d_out, int out_size)
{
    const float* image   = (const float*)d_in[0];
    const float* section = (const float*)d_in[1];
    const float* h0      = (const float*)d_in[2];
    const float* c0      = (const float*)d_in[3];
    const float* conv1_k = (const float*)d_in[4];
    const float* conv1_b = (const float*)d_in[5];
    const float* conv2_k = (const float*)d_in[6];
    const float* conv2_b = (const float*)d_in[7];
    const float* dense_w = (const float*)d_in[8];
    const float* dense_b = (const float*)d_in[9];
    const float* lstm_k  = (const float*)d_in[10];
    const float* lstm_rk = (const float*)d_in[11];
    const float* lstm_b  = (const float*)d_in[12];
    const float* nsc_w1  = (const float*)d_in[13];
    const float* nsc_b1  = (const float*)d_in[14];
    const float* nsc_w2  = (const float*)d_in[15];
    const float* nsc_b2  = (const float*)d_in[16];
    float* out = (float*)d_out;

    static int attr_done = 0;
    if (!attr_done) {
        cudaFuncSetAttribute(k1_mixed,
                             cudaFuncAttributeMaxDynamicSharedMemorySize, 56 * 1024);
        cudaFuncSetAttribute(k3_lstm_in,
                             cudaFuncAttributeMaxDynamicSharedMemorySize, 56 * 1024);
        attr_done = 1;
    }
    const int lstm_smem = (64 * 132 + 128 * 36) * 4;   // 52224 B

    k1_mixed<<<128, 256, lstm_smem>>>(image, section, conv1_k, conv1_b,
                                      conv2_k, conv2_b, dense_b, nsc_b1,
                                      h0, lstm_rk);
    k2_dense<<<128, 256>>>(dense_w);
    k3_lstm_in<<<64, 256, lstm_smem>>>(lstm_k);
    k4_gates<<<B, 256>>>(c0, lstm_b, out);
    k5_nsc1<<<64, 256>>>(nsc_w1, out);
    k6_nsc2<<<B, 96>>>(nsc_w2, nsc_b2, out);
}